// round 1
// baseline (speedup 1.0000x reference)
#include <cuda_runtime.h>
#include <cstdint>
#include <cstdio>

#define Hdim 256
#define Sdim 512
#define Bdim 256
#define G3   768   // 3*H

// 402 MB scratch for precomputed input-gate activations gi[b*S + t][768]
__device__ float g_gi[(size_t)Bdim * Sdim * G3];

// ---------------------------------------------------------------------------
// Kernel 1: gi = x @ W_ih^T + b_ih for all timesteps.
// A[m,k] = seq_states[b, k, t]  with m = b*512 + t  (contiguous along t).
// Tile: 128(M) x 128(N) x 32(K), 256 threads, 8x8 micro-tile (split 4+4).
// ---------------------------------------------------------------------------
__global__ __launch_bounds__(256) void gi_gemm_kernel(const float* __restrict__ seq,
                                                      const float* __restrict__ W_ih,
                                                      const float* __restrict__ b_ih) {
    __shared__ float As[32 * 128];   // [k][m]
    __shared__ float Ws[32 * 132];   // [k][n], padded row (132) for conflict-free
    const int tid = threadIdx.x;
    const int b   = blockIdx.x >> 2;
    const int t0  = (blockIdx.x & 3) * 128;
    const int n0  = blockIdx.y * 128;
    const float* seqb = seq + (size_t)b * (Hdim * Sdim);

    const int tm = (tid & 15) * 4;   // m fragment base (and +64)
    const int tn = (tid >> 4) * 4;   // n fragment base (and +64)
    const int lane = tid & 31, wp = tid >> 5;

    float acc[8][8];
#pragma unroll
    for (int i = 0; i < 8; ++i)
#pragma unroll
        for (int j = 0; j < 8; ++j) acc[i][j] = 0.f;

    for (int kt = 0; kt < 8; ++kt) {
        // Load A tile: 32k x 128m, coalesced float4 along t
        int pos = tid;
#pragma unroll
        for (int i = 0; i < 4; ++i, pos += 256) {
            int k  = pos >> 5;
            int mq = (pos & 31) << 2;
            float4 v = *(const float4*)(seqb + (size_t)(kt * 32 + k) * Sdim + t0 + mq);
            *(float4*)&As[k * 128 + mq] = v;
        }
        // Load W tile: each warp loads 16 n-rows; lane = k (coalesced 128B)
#pragma unroll
        for (int i = 0; i < 16; ++i) {
            int n = wp * 16 + i;
            Ws[lane * 132 + n] = W_ih[(size_t)(n0 + n) * Hdim + kt * 32 + lane];
        }
        __syncthreads();
#pragma unroll
        for (int kk = 0; kk < 32; ++kk) {
            float4 a0 = *(const float4*)&As[kk * 128 + tm];
            float4 a1 = *(const float4*)&As[kk * 128 + tm + 64];
            float4 w0 = *(const float4*)&Ws[kk * 132 + tn];
            float4 w1 = *(const float4*)&Ws[kk * 132 + tn + 64];
            float am[8] = {a0.x, a0.y, a0.z, a0.w, a1.x, a1.y, a1.z, a1.w};
            float wn[8] = {w0.x, w0.y, w0.z, w0.w, w1.x, w1.y, w1.z, w1.w};
#pragma unroll
            for (int i = 0; i < 8; ++i)
#pragma unroll
                for (int j = 0; j < 8; ++j) acc[i][j] = fmaf(am[i], wn[j], acc[i][j]);
        }
        __syncthreads();
    }

    // Epilogue: add bias, store float4s
    float4 bias0 = *(const float4*)&b_ih[n0 + tn];
    float4 bias1 = *(const float4*)&b_ih[n0 + tn + 64];
    float bs[8] = {bias0.x, bias0.y, bias0.z, bias0.w, bias1.x, bias1.y, bias1.z, bias1.w};
#pragma unroll
    for (int i = 0; i < 8; ++i) {
        int m = (i < 4) ? (tm + i) : (tm + 60 + i);  // tm+i or tm+64+(i-4)
        float* orow = g_gi + ((size_t)b * Sdim + t0 + m) * G3 + n0;
        float4 o0 = make_float4(acc[i][0] + bs[0], acc[i][1] + bs[1],
                                acc[i][2] + bs[2], acc[i][3] + bs[3]);
        float4 o1 = make_float4(acc[i][4] + bs[4], acc[i][5] + bs[5],
                                acc[i][6] + bs[6], acc[i][7] + bs[7]);
        *(float4*)(orow + tn)      = o0;
        *(float4*)(orow + tn + 64) = o1;
    }
}

// ---------------------------------------------------------------------------
// Kernel 2: persistent GRU recurrence.
// 32 clusters x 4 CTAs; cluster c handles batch rows [8c, 8c+8); CTA rank r
// owns h-dims [64r, 64r+64) and W_hh rows {k, k+256, k+512} for those dims.
// Per step: per-thread 3 dot products (r,z,n gates) for 2 batch rows,
// GRU epilogue, DSMEM broadcast of new h slice, cluster barrier.
// ---------------------------------------------------------------------------
#define WPAD 257
#define SMEM_FLOATS (192 * WPAD + 2 * 8 * 256 + 8)
#define SMEM_BYTES  (SMEM_FLOATS * 4)

__global__ __launch_bounds__(256, 1) __cluster_dims__(4, 1, 1)
void gru_rec_kernel(const float* __restrict__ tree,
                    const int*   __restrict__ mask,
                    const float* __restrict__ W_hh,
                    const float* __restrict__ b_hh,
                    float*       __restrict__ out) {
    extern __shared__ float sm[];
    float* W_s   = sm;                       // [192][257]
    float* h_buf = sm + 192 * WPAD;          // [2][8][256] ping-pong, full h
    int*   li_s  = (int*)(h_buf + 2 * 8 * 256);

    const int tid = threadIdx.x;
    const int r   = blockIdx.x & 3;          // cluster rank (1-D cluster)
    const int b0  = (blockIdx.x >> 2) * 8;   // first batch row of this cluster

    // Load W_hh slice: local row lr = g*64 + kk  <->  global row g*256 + r*64 + kk
    for (int lr = 0; lr < 192; ++lr) {
        int g = lr >> 6, kk = lr & 63;
        int j = g * 256 + r * 64 + kk;
        W_s[lr * WPAD + tid] = W_hh[(size_t)j * 256 + tid];
    }
    // h0 (each CTA keeps the full 8x256 state)
    for (int i = tid; i < 8 * 256; i += 256)
        h_buf[i] = tree[(size_t)b0 * 256 + i];
    // last_idx[b] = max(sum(mask[b,:]) - 1, 0): one warp per row
    {
        int bb = tid >> 5, lane = tid & 31;
        int s = 0;
        for (int i = lane; i < 512; i += 32) s += mask[(size_t)(b0 + bb) * 512 + i];
#pragma unroll
        for (int o = 16; o; o >>= 1) s += __shfl_xor_sync(0xffffffffu, s, o);
        if (lane == 0) li_s[bb] = (s > 0) ? (s - 1) : 0;
    }
    __syncthreads();
    asm volatile("barrier.cluster.arrive.aligned;" ::: "memory");
    asm volatile("barrier.cluster.wait.aligned;" ::: "memory");

    const int bq = tid >> 6;       // 0..3 -> batch pair
    const int jt = tid & 63;       // local h-dim
    const int bA = bq * 2, bB = bq * 2 + 1;
    const int kglob = r * 64 + jt;
    const float* wr = W_s + (      jt) * WPAD;
    const float* wz = W_s + ( 64 + jt) * WPAD;
    const float* wn = W_s + (128 + jt) * WPAD;
    const float bhr = b_hh[kglob];
    const float bhz = b_hh[256 + kglob];
    const float bhn = b_hh[512 + kglob];
    const int liA = li_s[bA], liB = li_s[bB];

    uint32_t hb_u32;
    asm("{ .reg .u64 t0; cvta.to.shared.u64 t0, %1; cvt.u32.u64 %0, t0; }"
        : "=r"(hb_u32) : "l"(h_buf));

    int p = 0;
    for (int t = 0; t < Sdim; ++t) {
        // Prefetch gi for this step (consumed after the dot loop -> latency hidden)
        const float* gA = g_gi + ((size_t)(b0 + bA) * Sdim + t) * G3 + kglob;
        const float* gB = g_gi + ((size_t)(b0 + bB) * Sdim + t) * G3 + kglob;
        float irA = gA[0], izA = gA[256], inA = gA[512];
        float irB = gB[0], izB = gB[256], inB = gB[512];

        const float* hA = h_buf + (size_t)(p * 8 + bA) * 256;
        const float* hB = h_buf + (size_t)(p * 8 + bB) * 256;
        float arA = bhr, azA = bhz, anA = bhn;
        float arB = bhr, azB = bhz, anB = bhn;
#pragma unroll 8
        for (int k = 0; k < 256; ++k) {
            float w0 = wr[k], w1 = wz[k], w2 = wn[k];
            float ha = hA[k], hb2 = hB[k];
            arA = fmaf(w0, ha, arA);  azA = fmaf(w1, ha, azA);  anA = fmaf(w2, ha, anA);
            arB = fmaf(w0, hb2, arB); azB = fmaf(w1, hb2, azB); anB = fmaf(w2, hb2, anB);
        }
        // GRU cell epilogue (all three gates local to this thread)
        float rA = 1.f / (1.f + __expf(-(irA + arA)));
        float zA = 1.f / (1.f + __expf(-(izA + azA)));
        float nA = tanhf(inA + rA * anA);
        float hnA = fmaf(zA, hA[kglob] - nA, nA);     // (1-z)n + z h

        float rB = 1.f / (1.f + __expf(-(irB + arB)));
        float zB = 1.f / (1.f + __expf(-(izB + azB)));
        float nB = tanhf(inB + rB * anB);
        float hnB = fmaf(zB, hB[kglob] - nB, nB);

        if (t == liA) out[(size_t)(b0 + bA) * 256 + kglob] = hnA;
        if (t == liB) out[(size_t)(b0 + bB) * 256 + kglob] = hnB;

        // Broadcast new h slice to all 4 cluster CTAs (incl. self) via DSMEM
        int pn = p ^ 1;
        uint32_t aA = hb_u32 + (uint32_t)(((pn * 8 + bA) * 256 + kglob) * 4);
        uint32_t aB = hb_u32 + (uint32_t)(((pn * 8 + bB) * 256 + kglob) * 4);
#pragma unroll
        for (int q = 0; q < 4; ++q) {
            asm volatile("{ .reg .b32 ra; mapa.shared::cluster.u32 ra, %0, %2; "
                         "st.shared::cluster.f32 [ra], %1; }"
                         :: "r"(aA), "f"(hnA), "r"(q) : "memory");
            asm volatile("{ .reg .b32 ra; mapa.shared::cluster.u32 ra, %0, %2; "
                         "st.shared::cluster.f32 [ra], %1; }"
                         :: "r"(aB), "f"(hnB), "r"(q) : "memory");
        }
        asm volatile("barrier.cluster.arrive.aligned;" ::: "memory");
        asm volatile("barrier.cluster.wait.aligned;" ::: "memory");
        p = pn;
    }
}

// ---------------------------------------------------------------------------
extern "C" void kernel_launch(void* const* d_in, const int* in_sizes, int n_in,
                              void* d_out, int out_size) {
    const float* tree  = (const float*)d_in[0];  // (B,H)
    const float* seq   = (const float*)d_in[1];  // (B,H,S)
    const int*   mask  = (const int*)  d_in[2];  // (B,S)
    const float* W_ih  = (const float*)d_in[3];  // (3H,H)
    const float* W_hh  = (const float*)d_in[4];  // (3H,H)
    const float* b_ih  = (const float*)d_in[5];  // (3H,)
    const float* b_hh  = (const float*)d_in[6];  // (3H,)
    float* out = (float*)d_out;

    // 1) precompute gi for all (b,t)
    dim3 g1((Bdim * Sdim) / 128, G3 / 128);
    gi_gemm_kernel<<<g1, 256>>>(seq, W_ih, b_ih);

    // 2) persistent clustered recurrence
    cudaFuncSetAttribute(gru_rec_kernel,
                         cudaFuncAttributeMaxDynamicSharedMemorySize, SMEM_BYTES);
    gru_rec_kernel<<<128, 256, SMEM_BYTES>>>(tree, mask, W_hh, b_hh, out);
}